// round 6
// baseline (speedup 1.0000x reference)
#include <cuda_runtime.h>
#include <math.h>
#include <float.h>

#define NN 50000
#define EE 800000
#define E2 (EE + NN)      // edges + self loops = 850000
#define ETEST 100000
#define ETOT 200000

// ---------------- scratch (device globals) ----------------------------------
__device__ __align__(16) float g_h1[NN * 64];
__device__ __align__(16) float g_as1[NN * 8];
__device__ __align__(16) float g_ad1[NN * 8];
__device__ __align__(16) float g_z1[NN * 64];

__device__ __align__(16) float g_h2[NN * 64];
__device__ __align__(16) float g_as2[NN];
__device__ __align__(16) float g_ad2[NN];
__device__ __align__(16) float g_z2[NN * 64];

__device__ __align__(16) int g_deg[NN];
__device__ __align__(16) int g_off[NN + 1];
__device__ __align__(16) int g_cur[NN];
__device__ __align__(16) int g_csr_src[E2];

// ---------------- helpers --------------------------------------------------
__device__ __forceinline__ float lrelu(float x) { return x > 0.0f ? x : 0.2f * x; }

__device__ __forceinline__ float dot4(float4 a, float4 b) {
    return fmaf(a.x, b.x, fmaf(a.y, b.y, fmaf(a.z, b.z, a.w * b.w)));
}

// ---------------- CSR build -------------------------------------------------
__global__ void zero_deg() {
    int t = blockIdx.x * blockDim.x + threadIdx.x;
    if (t < NN) g_deg[t] = 0;
}

__global__ __launch_bounds__(256) void count_deg(const int* __restrict__ ei) {
    int e0 = (blockIdx.x * blockDim.x + threadIdx.x) * 8;
#pragma unroll
    for (int j = 0; j < 8; j++) {
        int e = e0 + j;
        if (e < E2) {
            int d = (e < EE) ? ei[EE + e] : (e - EE);
            atomicAdd(&g_deg[d], 1);
        }
    }
}

__global__ void scan_kernel() {
    __shared__ int ssum[1024];
    const int CH = (NN + 1023) / 1024;  // 49
    int t = threadIdx.x;
    int base = t * CH;
    int s = 0;
    for (int i = 0; i < CH; i++) {
        int idx = base + i;
        if (idx < NN) s += g_deg[idx];
    }
    ssum[t] = s;
    __syncthreads();
    for (int off = 1; off < 1024; off <<= 1) {
        int v = (t >= off) ? ssum[t - off] : 0;
        __syncthreads();
        ssum[t] += v;
        __syncthreads();
    }
    int run = (t == 0) ? 0 : ssum[t - 1];
    for (int i = 0; i < CH; i++) {
        int idx = base + i;
        if (idx < NN) {
            g_off[idx] = run;
            g_cur[idx] = run;
            run += g_deg[idx];
        }
    }
    if (t == 1023) g_off[NN] = E2;
}

__global__ __launch_bounds__(256) void scatter_kernel(const int* __restrict__ ei) {
    int e0 = (blockIdx.x * blockDim.x + threadIdx.x) * 8;
#pragma unroll
    for (int j = 0; j < 8; j++) {
        int e = e0 + j;
        if (e < E2) {
            int s, d;
            if (e < EE) { s = ei[e]; d = ei[EE + e]; }
            else        { s = e - EE; d = s; }
            int pos = atomicAdd(&g_cur[d], 1);
            g_csr_src[pos] = s;
        }
    }
}

// ---------------- fused GEMM + attention scores ------------------------------
// [NN,K] @ [K,64]; block tile 64 rows x 64 cols, 256 threads, thread tile 4x4.
template <int K, int LAYER>
__global__ __launch_bounds__(256) void gemm_att(
        const float* __restrict__ Xin, const float* __restrict__ W,
        const float* __restrict__ att_s, const float* __restrict__ att_d) {
    __shared__ float xs[64 * 64];
    __shared__ float ws[64 * 64];
    const float* X = (LAYER == 1) ? Xin : g_z1;
    float* H = (LAYER == 1) ? g_h1 : g_h2;

    int tid = threadIdx.x;
    int cg = tid & 15;        // col group (4 cols)
    int rg = tid >> 4;        // row group (4 rows)
    int rowBase = blockIdx.x * 64;

    float acc[4][4];
#pragma unroll
    for (int a = 0; a < 4; a++)
#pragma unroll
        for (int b = 0; b < 4; b++) acc[a][b] = 0.f;

    const float4* X4 = reinterpret_cast<const float4*>(X);
    const float4* W4 = reinterpret_cast<const float4*>(W);

    for (int kc = 0; kc < K; kc += 64) {
#pragma unroll
        for (int i = tid; i < 1024; i += 256) {
            int row = i >> 4, q = i & 15;
            float4 v = (rowBase + row < NN)
                ? X4[(size_t)(rowBase + row) * (K / 4) + (kc / 4) + q]
                : make_float4(0.f, 0.f, 0.f, 0.f);
            *reinterpret_cast<float4*>(&xs[row * 64 + q * 4]) = v;
        }
#pragma unroll
        for (int i = tid; i < 1024; i += 256) {
            *reinterpret_cast<float4*>(&ws[i * 4]) = W4[kc * 16 + i];
        }
        __syncthreads();

#pragma unroll 4
        for (int k = 0; k < 64; k++) {
            float4 wv = *reinterpret_cast<const float4*>(&ws[k * 64 + cg * 4]);
            float x0 = xs[(rg * 4 + 0) * 64 + k];
            float x1 = xs[(rg * 4 + 1) * 64 + k];
            float x2 = xs[(rg * 4 + 2) * 64 + k];
            float x3 = xs[(rg * 4 + 3) * 64 + k];
            acc[0][0] = fmaf(x0, wv.x, acc[0][0]); acc[0][1] = fmaf(x0, wv.y, acc[0][1]);
            acc[0][2] = fmaf(x0, wv.z, acc[0][2]); acc[0][3] = fmaf(x0, wv.w, acc[0][3]);
            acc[1][0] = fmaf(x1, wv.x, acc[1][0]); acc[1][1] = fmaf(x1, wv.y, acc[1][1]);
            acc[1][2] = fmaf(x1, wv.z, acc[1][2]); acc[1][3] = fmaf(x1, wv.w, acc[1][3]);
            acc[2][0] = fmaf(x2, wv.x, acc[2][0]); acc[2][1] = fmaf(x2, wv.y, acc[2][1]);
            acc[2][2] = fmaf(x2, wv.z, acc[2][2]); acc[2][3] = fmaf(x2, wv.w, acc[2][3]);
            acc[3][0] = fmaf(x3, wv.x, acc[3][0]); acc[3][1] = fmaf(x3, wv.y, acc[3][1]);
            acc[3][2] = fmaf(x3, wv.z, acc[3][2]); acc[3][3] = fmaf(x3, wv.w, acc[3][3]);
        }
        __syncthreads();
    }

    float aw_s[4], aw_d[4];
#pragma unroll
    for (int cc = 0; cc < 4; cc++) {
        aw_s[cc] = __ldg(&att_s[cg * 4 + cc]);
        aw_d[cc] = __ldg(&att_d[cg * 4 + cc]);
    }

#pragma unroll
    for (int rr = 0; rr < 4; rr++) {
        int row = rowBase + rg * 4 + rr;
        bool ok = row < NN;
        if (ok) {
            float4 hv = make_float4(acc[rr][0], acc[rr][1], acc[rr][2], acc[rr][3]);
            *reinterpret_cast<float4*>(&H[(size_t)row * 64 + cg * 4]) = hv;
        }
        float ps = 0.f, pd = 0.f;
#pragma unroll
        for (int cc = 0; cc < 4; cc++) {
            ps = fmaf(acc[rr][cc], aw_s[cc], ps);
            pd = fmaf(acc[rr][cc], aw_d[cc], pd);
        }
        if (LAYER == 1) {
            ps += __shfl_xor_sync(0xffffffffu, ps, 1);
            pd += __shfl_xor_sync(0xffffffffu, pd, 1);
            if (!(cg & 1) && ok) {
                g_as1[row * 8 + (cg >> 1)] = ps;
                g_ad1[row * 8 + (cg >> 1)] = pd;
            }
        } else {
            ps += __shfl_xor_sync(0xffffffffu, ps, 1);
            pd += __shfl_xor_sync(0xffffffffu, pd, 1);
            ps += __shfl_xor_sync(0xffffffffu, ps, 2);
            pd += __shfl_xor_sync(0xffffffffu, pd, 2);
            ps += __shfl_xor_sync(0xffffffffu, ps, 4);
            pd += __shfl_xor_sync(0xffffffffu, pd, 4);
            ps += __shfl_xor_sync(0xffffffffu, ps, 8);
            pd += __shfl_xor_sync(0xffffffffu, pd, 8);
            if (cg == 0 && ok) {
                g_as2[row] = ps;
                g_ad2[row] = pd;
            }
        }
    }
}

// ---------------- layer-1 aggregation: warp per dst (H=8, C=8) --------------
__global__ __launch_bounds__(256) void agg1_kernel(const float* __restrict__ bias) {
    int warp = (blockIdx.x * blockDim.x + threadIdx.x) >> 5;
    int lane = threadIdx.x & 31;
    if (warp >= NN) return;
    int d = warp;
    int beg = g_off[d], end = g_off[d + 1];

    float adh = (lane < 8) ? g_ad1[d * 8 + lane] : 0.f;
    int h0 = lane >> 3;
    int h1i = 4 + (lane >> 3);

    float num0 = 0.f, num1 = 0.f, den0 = 0.f, den1 = 0.f;
    int s = (beg < end) ? g_csr_src[beg] : 0;
    float aS = (lane < 8) ? g_as1[s * 8 + lane] : 0.f;
    float v0 = g_h1[s * 64 + lane];
    float v1 = g_h1[s * 64 + 32 + lane];
    for (int i = beg; i < end; i++) {
        int snext = 0; float aSn = 0.f, v0n = 0.f, v1n = 0.f;
        if (i + 1 < end) {
            snext = g_csr_src[i + 1];
            if (lane < 8) aSn = g_as1[snext * 8 + lane];
            v0n = g_h1[snext * 64 + lane];
            v1n = g_h1[snext * 64 + 32 + lane];
        }
        float a = (lane < 8) ? __expf(lrelu(aS + adh)) : 0.f;
        float e0 = __shfl_sync(0xffffffffu, a, h0);
        float e1 = __shfl_sync(0xffffffffu, a, h1i);
        num0 = fmaf(e0, v0, num0); den0 += e0;
        num1 = fmaf(e1, v1, num1); den1 += e1;
        s = snext; aS = aSn; v0 = v0n; v1 = v1n;
    }
    float o0 = num0 / fmaxf(den0, 1e-16f) + bias[lane];
    float o1 = num1 / fmaxf(den1, 1e-16f) + bias[32 + lane];
    g_z1[d * 64 + lane]      = o0 > 0.f ? o0 : expm1f(o0);  // ELU
    g_z1[d * 64 + 32 + lane] = o1 > 0.f ? o1 : expm1f(o1);
}

// ---------------- layer-2 aggregation: warp per dst (H=1, C=64) -------------
__global__ __launch_bounds__(256) void agg2_kernel(const float* __restrict__ bias) {
    int warp = (blockIdx.x * blockDim.x + threadIdx.x) >> 5;
    int lane = threadIdx.x & 31;
    if (warp >= NN) return;
    int d = warp;
    int beg = g_off[d], end = g_off[d + 1];

    float ad = g_ad2[d];
    float num0 = 0.f, num1 = 0.f, den = 0.f;
    int s = (beg < end) ? g_csr_src[beg] : 0;
    float aS = g_as2[s];
    float v0 = g_h2[s * 64 + lane];
    float v1 = g_h2[s * 64 + 32 + lane];
    for (int i = beg; i < end; i++) {
        int snext = 0; float aSn = 0.f, v0n = 0.f, v1n = 0.f;
        if (i + 1 < end) {
            snext = g_csr_src[i + 1];
            aSn = g_as2[snext];
            v0n = g_h2[snext * 64 + lane];
            v1n = g_h2[snext * 64 + 32 + lane];
        }
        float ex = __expf(lrelu(aS + ad));
        num0 = fmaf(ex, v0, num0);
        num1 = fmaf(ex, v1, num1);
        den += ex;
        s = snext; aS = aSn; v0 = v0n; v1 = v1n;
    }
    float inv = 1.0f / fmaxf(den, 1e-16f);
    g_z2[d * 64 + lane]      = num0 * inv + bias[lane];
    g_z2[d * 64 + 32 + lane] = num1 * inv + bias[32 + lane];
}

// ---------------- link prediction logits -----------------------------------
__global__ __launch_bounds__(256) void logits_kernel(const int* __restrict__ pos,
                                                     const int* __restrict__ neg,
                                                     float* __restrict__ out) {
    int t = blockIdx.x * blockDim.x + threadIdx.x;
    if (t >= ETOT) return;
    int s, d;
    if (t < ETEST) { s = pos[t]; d = pos[ETEST + t]; }
    else           { s = neg[t - ETEST]; d = neg[ETEST + (t - ETEST)]; }
    const float4* a = reinterpret_cast<const float4*>(g_z2) + (size_t)s * 16;
    const float4* b = reinterpret_cast<const float4*>(g_z2) + (size_t)d * 16;
    float acc = 0.f;
#pragma unroll
    for (int i = 0; i < 16; i++) acc += dot4(a[i], b[i]);
    out[t] = acc;
}

// ---------------- launch ----------------------------------------------------
extern "C" void kernel_launch(void* const* d_in, const int* in_sizes, int n_in,
                              void* d_out, int out_size) {
    const float* x    = (const float*)d_in[0];
    const int*   ei   = (const int*)d_in[1];
    const int*   pos  = (const int*)d_in[2];
    const int*   neg  = (const int*)d_in[3];
    const float* W1   = (const float*)d_in[4];
    const float* as1  = (const float*)d_in[5];
    const float* ad1  = (const float*)d_in[6];
    const float* b1   = (const float*)d_in[7];
    const float* W2   = (const float*)d_in[8];
    const float* as2  = (const float*)d_in[9];
    const float* ad2  = (const float*)d_in[10];
    const float* b2   = (const float*)d_in[11];
    float* out = (float*)d_out;

    const int TB = 256;
    const int E8 = (E2 + 7) / 8;

    // Fork a side stream for the CSR build (independent of gemm1).
    // Created per call; kernel_launch only runs for correctness + capture,
    // so the handful of leaked handles is bounded and capture-legal.
    cudaStream_t s2;
    cudaStreamCreateWithFlags(&s2, cudaStreamNonBlocking);
    cudaEvent_t evFork, evJoin;
    cudaEventCreateWithFlags(&evFork, cudaEventDisableTiming);
    cudaEventCreateWithFlags(&evJoin, cudaEventDisableTiming);

    cudaEventRecord(evFork, 0);
    cudaStreamWaitEvent(s2, evFork, 0);

    // side stream: CSR build
    zero_deg<<<(NN + TB - 1) / TB, TB, 0, s2>>>();
    count_deg<<<(E8 + TB - 1) / TB, TB, 0, s2>>>(ei);
    scan_kernel<<<1, 1024, 0, s2>>>();
    scatter_kernel<<<(E8 + TB - 1) / TB, TB, 0, s2>>>(ei);
    cudaEventRecord(evJoin, s2);

    // main stream: layer-1 GEMM + attention scores (independent of CSR)
    gemm_att<128, 1><<<(NN + 63) / 64, TB>>>(x, W1, as1, ad1);

    // join: aggregation needs both
    cudaStreamWaitEvent(0, evJoin, 0);
    agg1_kernel<<<(NN * 32 + TB - 1) / TB, TB>>>(b1);
    // layer 2
    gemm_att<64, 2><<<(NN + 63) / 64, TB>>>(nullptr, W2, as2, ad2);
    agg2_kernel<<<(NN * 32 + TB - 1) / TB, TB>>>(b2);
    // logits
    logits_kernel<<<(ETOT + TB - 1) / TB, TB>>>(pos, neg, out);
}

// round 7
// speedup vs baseline: 1.1313x; 1.1313x over previous
#include <cuda_runtime.h>
#include <math.h>
#include <float.h>

#define NN 50000
#define EE 800000
#define E2 (EE + NN)      // edges + self loops = 850000
#define ETEST 100000
#define ETOT 200000

// ---------------- scratch (device globals) ----------------------------------
__device__ __align__(16) float g_h1[NN * 64];
__device__ __align__(16) float g_as1[NN * 8];
__device__ __align__(16) float g_ad1[NN * 8];
__device__ __align__(16) float g_z1[NN * 64];

__device__ __align__(16) float g_h2[NN * 64];
__device__ __align__(16) float g_as2[NN];
__device__ __align__(16) float g_ad2[NN];
__device__ __align__(16) float g_z2[NN * 64];

__device__ __align__(16) int g_deg[NN];
__device__ __align__(16) int g_off[NN + 1];
__device__ __align__(16) int g_cur[NN];
__device__ __align__(16) int g_csr_src[E2];

// ---------------- helpers --------------------------------------------------
__device__ __forceinline__ float lrelu(float x) { return x > 0.0f ? x : 0.2f * x; }

__device__ __forceinline__ float dot4(float4 a, float4 b) {
    return fmaf(a.x, b.x, fmaf(a.y, b.y, fmaf(a.z, b.z, a.w * b.w)));
}

// ---------------- CSR build -------------------------------------------------
__global__ void zero_deg() {
    int t = blockIdx.x * blockDim.x + threadIdx.x;
    if (t < NN) g_deg[t] = 0;
}

__global__ __launch_bounds__(256) void count_deg(const int* __restrict__ ei) {
    int e0 = (blockIdx.x * blockDim.x + threadIdx.x) * 4;
#pragma unroll
    for (int j = 0; j < 4; j++) {
        int e = e0 + j;
        if (e < E2) {
            int d = (e < EE) ? ei[EE + e] : (e - EE);
            atomicAdd(&g_deg[d], 1);
        }
    }
}

__global__ void scan_kernel() {
    __shared__ int ssum[1024];
    const int CH = (NN + 1023) / 1024;  // 49
    int t = threadIdx.x;
    int base = t * CH;
    int s = 0;
    for (int i = 0; i < CH; i++) {
        int idx = base + i;
        if (idx < NN) s += g_deg[idx];
    }
    ssum[t] = s;
    __syncthreads();
    for (int off = 1; off < 1024; off <<= 1) {
        int v = (t >= off) ? ssum[t - off] : 0;
        __syncthreads();
        ssum[t] += v;
        __syncthreads();
    }
    int run = (t == 0) ? 0 : ssum[t - 1];
    for (int i = 0; i < CH; i++) {
        int idx = base + i;
        if (idx < NN) {
            g_off[idx] = run;
            g_cur[idx] = run;
            run += g_deg[idx];
        }
    }
    if (t == 1023) g_off[NN] = E2;
}

__global__ __launch_bounds__(256) void scatter_kernel(const int* __restrict__ ei) {
    int e0 = (blockIdx.x * blockDim.x + threadIdx.x) * 4;
#pragma unroll
    for (int j = 0; j < 4; j++) {
        int e = e0 + j;
        if (e < E2) {
            int s, d;
            if (e < EE) { s = ei[e]; d = ei[EE + e]; }
            else        { s = e - EE; d = s; }
            int pos = atomicAdd(&g_cur[d], 1);
            g_csr_src[pos] = s;
        }
    }
}

// ---------------- fused GEMM + attention scores ------------------------------
// [NN,K] @ [K,64]; block tile 64 rows x 64 cols, 256 threads, thread tile 4x4.
template <int K, int LAYER>
__global__ __launch_bounds__(256) void gemm_att(
        const float* __restrict__ Xin, const float* __restrict__ W,
        const float* __restrict__ att_s, const float* __restrict__ att_d) {
    __shared__ float xs[64 * 64];
    __shared__ float ws[64 * 64];
    const float* X = (LAYER == 1) ? Xin : g_z1;
    float* H = (LAYER == 1) ? g_h1 : g_h2;

    int tid = threadIdx.x;
    int cg = tid & 15;        // col group (4 cols)
    int rg = tid >> 4;        // row group (4 rows)
    int rowBase = blockIdx.x * 64;

    float acc[4][4];
#pragma unroll
    for (int a = 0; a < 4; a++)
#pragma unroll
        for (int b = 0; b < 4; b++) acc[a][b] = 0.f;

    const float4* X4 = reinterpret_cast<const float4*>(X);
    const float4* W4 = reinterpret_cast<const float4*>(W);

    for (int kc = 0; kc < K; kc += 64) {
#pragma unroll
        for (int i = tid; i < 1024; i += 256) {
            int row = i >> 4, q = i & 15;
            float4 v = (rowBase + row < NN)
                ? X4[(size_t)(rowBase + row) * (K / 4) + (kc / 4) + q]
                : make_float4(0.f, 0.f, 0.f, 0.f);
            *reinterpret_cast<float4*>(&xs[row * 64 + q * 4]) = v;
        }
#pragma unroll
        for (int i = tid; i < 1024; i += 256) {
            *reinterpret_cast<float4*>(&ws[i * 4]) = W4[kc * 16 + i];
        }
        __syncthreads();

#pragma unroll 4
        for (int k = 0; k < 64; k++) {
            float4 wv = *reinterpret_cast<const float4*>(&ws[k * 64 + cg * 4]);
            float x0 = xs[(rg * 4 + 0) * 64 + k];
            float x1 = xs[(rg * 4 + 1) * 64 + k];
            float x2 = xs[(rg * 4 + 2) * 64 + k];
            float x3 = xs[(rg * 4 + 3) * 64 + k];
            acc[0][0] = fmaf(x0, wv.x, acc[0][0]); acc[0][1] = fmaf(x0, wv.y, acc[0][1]);
            acc[0][2] = fmaf(x0, wv.z, acc[0][2]); acc[0][3] = fmaf(x0, wv.w, acc[0][3]);
            acc[1][0] = fmaf(x1, wv.x, acc[1][0]); acc[1][1] = fmaf(x1, wv.y, acc[1][1]);
            acc[1][2] = fmaf(x1, wv.z, acc[1][2]); acc[1][3] = fmaf(x1, wv.w, acc[1][3]);
            acc[2][0] = fmaf(x2, wv.x, acc[2][0]); acc[2][1] = fmaf(x2, wv.y, acc[2][1]);
            acc[2][2] = fmaf(x2, wv.z, acc[2][2]); acc[2][3] = fmaf(x2, wv.w, acc[2][3]);
            acc[3][0] = fmaf(x3, wv.x, acc[3][0]); acc[3][1] = fmaf(x3, wv.y, acc[3][1]);
            acc[3][2] = fmaf(x3, wv.z, acc[3][2]); acc[3][3] = fmaf(x3, wv.w, acc[3][3]);
        }
        __syncthreads();
    }

    float aw_s[4], aw_d[4];
#pragma unroll
    for (int cc = 0; cc < 4; cc++) {
        aw_s[cc] = __ldg(&att_s[cg * 4 + cc]);
        aw_d[cc] = __ldg(&att_d[cg * 4 + cc]);
    }

#pragma unroll
    for (int rr = 0; rr < 4; rr++) {
        int row = rowBase + rg * 4 + rr;
        bool ok = row < NN;
        if (ok) {
            float4 hv = make_float4(acc[rr][0], acc[rr][1], acc[rr][2], acc[rr][3]);
            *reinterpret_cast<float4*>(&H[(size_t)row * 64 + cg * 4]) = hv;
        }
        float ps = 0.f, pd = 0.f;
#pragma unroll
        for (int cc = 0; cc < 4; cc++) {
            ps = fmaf(acc[rr][cc], aw_s[cc], ps);
            pd = fmaf(acc[rr][cc], aw_d[cc], pd);
        }
        if (LAYER == 1) {
            ps += __shfl_xor_sync(0xffffffffu, ps, 1);
            pd += __shfl_xor_sync(0xffffffffu, pd, 1);
            if (!(cg & 1) && ok) {
                g_as1[row * 8 + (cg >> 1)] = ps;
                g_ad1[row * 8 + (cg >> 1)] = pd;
            }
        } else {
            ps += __shfl_xor_sync(0xffffffffu, ps, 1);
            pd += __shfl_xor_sync(0xffffffffu, pd, 1);
            ps += __shfl_xor_sync(0xffffffffu, ps, 2);
            pd += __shfl_xor_sync(0xffffffffu, pd, 2);
            ps += __shfl_xor_sync(0xffffffffu, ps, 4);
            pd += __shfl_xor_sync(0xffffffffu, pd, 4);
            ps += __shfl_xor_sync(0xffffffffu, ps, 8);
            pd += __shfl_xor_sync(0xffffffffu, pd, 8);
            if (cg == 0 && ok) {
                g_as2[row] = ps;
                g_ad2[row] = pd;
            }
        }
    }
}

// ---------------- layer-1 aggregation: warp per dst, unroll 2 ----------------
__global__ __launch_bounds__(256) void agg1_kernel(const float* __restrict__ bias) {
    int warp = (blockIdx.x * blockDim.x + threadIdx.x) >> 5;
    int lane = threadIdx.x & 31;
    if (warp >= NN) return;
    int d = warp;
    int beg = g_off[d], end = g_off[d + 1];

    float adh = (lane < 8) ? g_ad1[d * 8 + lane] : 0.f;
    int h0 = lane >> 3;
    int h1i = 4 + (lane >> 3);

    float num0 = 0.f, num1 = 0.f, den0 = 0.f, den1 = 0.f;
    float num0b = 0.f, num1b = 0.f, den0b = 0.f, den1b = 0.f;
    int i = beg;
    for (; i + 1 < end; i += 2) {
        int s0 = g_csr_src[i];
        int s1 = g_csr_src[i + 1];
        float a0 = (lane < 8) ? g_as1[s0 * 8 + lane] : 0.f;
        float a1 = (lane < 8) ? g_as1[s1 * 8 + lane] : 0.f;
        float v00 = g_h1[s0 * 64 + lane];
        float v01 = g_h1[s0 * 64 + 32 + lane];
        float v10 = g_h1[s1 * 64 + lane];
        float v11 = g_h1[s1 * 64 + 32 + lane];
        float e0v = (lane < 8) ? __expf(lrelu(a0 + adh)) : 0.f;
        float e1v = (lane < 8) ? __expf(lrelu(a1 + adh)) : 0.f;
        float e00 = __shfl_sync(0xffffffffu, e0v, h0);
        float e01 = __shfl_sync(0xffffffffu, e0v, h1i);
        float e10 = __shfl_sync(0xffffffffu, e1v, h0);
        float e11 = __shfl_sync(0xffffffffu, e1v, h1i);
        num0  = fmaf(e00, v00, num0);  den0  += e00;
        num1  = fmaf(e01, v01, num1);  den1  += e01;
        num0b = fmaf(e10, v10, num0b); den0b += e10;
        num1b = fmaf(e11, v11, num1b); den1b += e11;
    }
    if (i < end) {
        int s0 = g_csr_src[i];
        float a0 = (lane < 8) ? g_as1[s0 * 8 + lane] : 0.f;
        float v00 = g_h1[s0 * 64 + lane];
        float v01 = g_h1[s0 * 64 + 32 + lane];
        float e0v = (lane < 8) ? __expf(lrelu(a0 + adh)) : 0.f;
        float e00 = __shfl_sync(0xffffffffu, e0v, h0);
        float e01 = __shfl_sync(0xffffffffu, e0v, h1i);
        num0 = fmaf(e00, v00, num0); den0 += e00;
        num1 = fmaf(e01, v01, num1); den1 += e01;
    }
    num0 += num0b; den0 += den0b;
    num1 += num1b; den1 += den1b;
    float o0 = num0 / fmaxf(den0, 1e-16f) + bias[lane];
    float o1 = num1 / fmaxf(den1, 1e-16f) + bias[32 + lane];
    g_z1[d * 64 + lane]      = o0 > 0.f ? o0 : expm1f(o0);  // ELU
    g_z1[d * 64 + 32 + lane] = o1 > 0.f ? o1 : expm1f(o1);
}

// ---------------- layer-2 aggregation: warp per dst, unroll 2 ----------------
__global__ __launch_bounds__(256) void agg2_kernel(const float* __restrict__ bias) {
    int warp = (blockIdx.x * blockDim.x + threadIdx.x) >> 5;
    int lane = threadIdx.x & 31;
    if (warp >= NN) return;
    int d = warp;
    int beg = g_off[d], end = g_off[d + 1];

    float ad = g_ad2[d];
    float num0 = 0.f, num1 = 0.f, den = 0.f;
    float num0b = 0.f, num1b = 0.f, denb = 0.f;
    int i = beg;
    for (; i + 1 < end; i += 2) {
        int s0 = g_csr_src[i];
        int s1 = g_csr_src[i + 1];
        float a0 = g_as2[s0];
        float a1 = g_as2[s1];
        float v00 = g_h2[s0 * 64 + lane];
        float v01 = g_h2[s0 * 64 + 32 + lane];
        float v10 = g_h2[s1 * 64 + lane];
        float v11 = g_h2[s1 * 64 + 32 + lane];
        float e0 = __expf(lrelu(a0 + ad));
        float e1 = __expf(lrelu(a1 + ad));
        num0  = fmaf(e0, v00, num0);
        num1  = fmaf(e0, v01, num1);
        den  += e0;
        num0b = fmaf(e1, v10, num0b);
        num1b = fmaf(e1, v11, num1b);
        denb += e1;
    }
    if (i < end) {
        int s0 = g_csr_src[i];
        float e0 = __expf(lrelu(g_as2[s0] + ad));
        num0 = fmaf(e0, g_h2[s0 * 64 + lane], num0);
        num1 = fmaf(e0, g_h2[s0 * 64 + 32 + lane], num1);
        den += e0;
    }
    num0 += num0b; num1 += num1b; den += denb;
    float inv = 1.0f / fmaxf(den, 1e-16f);
    g_z2[d * 64 + lane]      = num0 * inv + bias[lane];
    g_z2[d * 64 + 32 + lane] = num1 * inv + bias[32 + lane];
}

// ---------------- link prediction logits -----------------------------------
__global__ __launch_bounds__(256) void logits_kernel(const int* __restrict__ pos,
                                                     const int* __restrict__ neg,
                                                     float* __restrict__ out) {
    int t = blockIdx.x * blockDim.x + threadIdx.x;
    if (t >= ETOT) return;
    int s, d;
    if (t < ETEST) { s = pos[t]; d = pos[ETEST + t]; }
    else           { s = neg[t - ETEST]; d = neg[ETEST + (t - ETEST)]; }
    const float4* a = reinterpret_cast<const float4*>(g_z2) + (size_t)s * 16;
    const float4* b = reinterpret_cast<const float4*>(g_z2) + (size_t)d * 16;
    float acc = 0.f;
#pragma unroll
    for (int i = 0; i < 16; i++) acc += dot4(a[i], b[i]);
    out[t] = acc;
}

// ---------------- launch ----------------------------------------------------
extern "C" void kernel_launch(void* const* d_in, const int* in_sizes, int n_in,
                              void* d_out, int out_size) {
    const float* x    = (const float*)d_in[0];
    const int*   ei   = (const int*)d_in[1];
    const int*   pos  = (const int*)d_in[2];
    const int*   neg  = (const int*)d_in[3];
    const float* W1   = (const float*)d_in[4];
    const float* as1  = (const float*)d_in[5];
    const float* ad1  = (const float*)d_in[6];
    const float* b1   = (const float*)d_in[7];
    const float* W2   = (const float*)d_in[8];
    const float* as2  = (const float*)d_in[9];
    const float* ad2  = (const float*)d_in[10];
    const float* b2   = (const float*)d_in[11];
    float* out = (float*)d_out;

    const int TB = 256;
    const int E4 = (E2 + 3) / 4;
    // CSR build
    zero_deg<<<(NN + TB - 1) / TB, TB>>>();
    count_deg<<<(E4 + TB - 1) / TB, TB>>>(ei);
    scan_kernel<<<1, 1024>>>();
    scatter_kernel<<<(E4 + TB - 1) / TB, TB>>>(ei);
    // layer 1 (GEMM + att fused)
    gemm_att<128, 1><<<(NN + 63) / 64, TB>>>(x, W1, as1, ad1);
    agg1_kernel<<<(NN * 32 + TB - 1) / TB, TB>>>(b1);
    // layer 2
    gemm_att<64, 2><<<(NN + 63) / 64, TB>>>(nullptr, W2, as2, ad2);
    agg2_kernel<<<(NN * 32 + TB - 1) / TB, TB>>>(b2);
    // logits
    logits_kernel<<<(ETOT + TB - 1) / TB, TB>>>(pos, neg, out);
}

// round 8
// speedup vs baseline: 1.1585x; 1.0240x over previous
#include <cuda_runtime.h>
#include <math.h>
#include <float.h>

#define NN 50000
#define EE 800000
#define E2 (EE + NN)      // edges + self loops = 850000
#define ETEST 100000
#define ETOT 200000

// ---------------- scratch (device globals) ----------------------------------
__device__ __align__(16) float g_h1[NN * 64];
__device__ __align__(16) float g_as1[NN * 8];
__device__ __align__(16) float g_ad1[NN * 8];
__device__ __align__(16) float g_z1[NN * 64];

__device__ __align__(16) float g_h2[NN * 64];
__device__ __align__(16) float g_as2[NN];
__device__ __align__(16) float g_ad2[NN];
__device__ __align__(16) float g_z2[NN * 64];

__device__ __align__(16) int g_deg[NN];
__device__ __align__(16) int g_off[NN + 1];
__device__ __align__(16) int g_cur[NN];
__device__ __align__(16) int g_csr_src[E2];

// ---------------- helpers --------------------------------------------------
__device__ __forceinline__ float lrelu(float x) { return x > 0.0f ? x : 0.2f * x; }

__device__ __forceinline__ float dot4(float4 a, float4 b) {
    return fmaf(a.x, b.x, fmaf(a.y, b.y, fmaf(a.z, b.z, a.w * b.w)));
}

// ---------------- CSR build -------------------------------------------------
__global__ void zero_deg() {
    int t = blockIdx.x * blockDim.x + threadIdx.x;
    if (t < NN) g_deg[t] = 0;
}

__global__ __launch_bounds__(256) void count_deg(const int* __restrict__ ei) {
    int e0 = (blockIdx.x * blockDim.x + threadIdx.x) * 4;
#pragma unroll
    for (int j = 0; j < 4; j++) {
        int e = e0 + j;
        if (e < E2) {
            int d = (e < EE) ? ei[EE + e] : (e - EE);
            atomicAdd(&g_deg[d], 1);
        }
    }
}

__global__ void scan_kernel() {
    __shared__ int ssum[1024];
    const int CH = (NN + 1023) / 1024;  // 49
    int t = threadIdx.x;
    int base = t * CH;
    int s = 0;
    for (int i = 0; i < CH; i++) {
        int idx = base + i;
        if (idx < NN) s += g_deg[idx];
    }
    ssum[t] = s;
    __syncthreads();
    for (int off = 1; off < 1024; off <<= 1) {
        int v = (t >= off) ? ssum[t - off] : 0;
        __syncthreads();
        ssum[t] += v;
        __syncthreads();
    }
    int run = (t == 0) ? 0 : ssum[t - 1];
    for (int i = 0; i < CH; i++) {
        int idx = base + i;
        if (idx < NN) {
            g_off[idx] = run;
            g_cur[idx] = run;
            run += g_deg[idx];
        }
    }
    if (t == 1023) g_off[NN] = E2;
}

__global__ __launch_bounds__(256) void scatter_kernel(const int* __restrict__ ei) {
    int e0 = (blockIdx.x * blockDim.x + threadIdx.x) * 4;
#pragma unroll
    for (int j = 0; j < 4; j++) {
        int e = e0 + j;
        if (e < E2) {
            int s, d;
            if (e < EE) { s = ei[e]; d = ei[EE + e]; }
            else        { s = e - EE; d = s; }
            int pos = atomicAdd(&g_cur[d], 1);
            g_csr_src[pos] = s;
        }
    }
}

// ---------------- fused GEMM + attention scores ------------------------------
// [NN,K] @ [K,64]; block tile 64 rows x 64 cols, 256 threads, thread tile 4x4.
template <int K, int LAYER>
__global__ __launch_bounds__(256) void gemm_att(
        const float* __restrict__ Xin, const float* __restrict__ W,
        const float* __restrict__ att_s, const float* __restrict__ att_d) {
    __shared__ float xs[64 * 64];
    __shared__ float ws[64 * 64];
    const float* X = (LAYER == 1) ? Xin : g_z1;
    float* H = (LAYER == 1) ? g_h1 : g_h2;

    int tid = threadIdx.x;
    int cg = tid & 15;        // col group (4 cols)
    int rg = tid >> 4;        // row group (4 rows)
    int rowBase = blockIdx.x * 64;

    float acc[4][4];
#pragma unroll
    for (int a = 0; a < 4; a++)
#pragma unroll
        for (int b = 0; b < 4; b++) acc[a][b] = 0.f;

    const float4* X4 = reinterpret_cast<const float4*>(X);
    const float4* W4 = reinterpret_cast<const float4*>(W);

    for (int kc = 0; kc < K; kc += 64) {
#pragma unroll
        for (int i = tid; i < 1024; i += 256) {
            int row = i >> 4, q = i & 15;
            float4 v = (rowBase + row < NN)
                ? X4[(size_t)(rowBase + row) * (K / 4) + (kc / 4) + q]
                : make_float4(0.f, 0.f, 0.f, 0.f);
            *reinterpret_cast<float4*>(&xs[row * 64 + q * 4]) = v;
        }
#pragma unroll
        for (int i = tid; i < 1024; i += 256) {
            *reinterpret_cast<float4*>(&ws[i * 4]) = W4[kc * 16 + i];
        }
        __syncthreads();

#pragma unroll 4
        for (int k = 0; k < 64; k++) {
            float4 wv = *reinterpret_cast<const float4*>(&ws[k * 64 + cg * 4]);
            float x0 = xs[(rg * 4 + 0) * 64 + k];
            float x1 = xs[(rg * 4 + 1) * 64 + k];
            float x2 = xs[(rg * 4 + 2) * 64 + k];
            float x3 = xs[(rg * 4 + 3) * 64 + k];
            acc[0][0] = fmaf(x0, wv.x, acc[0][0]); acc[0][1] = fmaf(x0, wv.y, acc[0][1]);
            acc[0][2] = fmaf(x0, wv.z, acc[0][2]); acc[0][3] = fmaf(x0, wv.w, acc[0][3]);
            acc[1][0] = fmaf(x1, wv.x, acc[1][0]); acc[1][1] = fmaf(x1, wv.y, acc[1][1]);
            acc[1][2] = fmaf(x1, wv.z, acc[1][2]); acc[1][3] = fmaf(x1, wv.w, acc[1][3]);
            acc[2][0] = fmaf(x2, wv.x, acc[2][0]); acc[2][1] = fmaf(x2, wv.y, acc[2][1]);
            acc[2][2] = fmaf(x2, wv.z, acc[2][2]); acc[2][3] = fmaf(x2, wv.w, acc[2][3]);
            acc[3][0] = fmaf(x3, wv.x, acc[3][0]); acc[3][1] = fmaf(x3, wv.y, acc[3][1]);
            acc[3][2] = fmaf(x3, wv.z, acc[3][2]); acc[3][3] = fmaf(x3, wv.w, acc[3][3]);
        }
        __syncthreads();
    }

    float aw_s[4], aw_d[4];
#pragma unroll
    for (int cc = 0; cc < 4; cc++) {
        aw_s[cc] = __ldg(&att_s[cg * 4 + cc]);
        aw_d[cc] = __ldg(&att_d[cg * 4 + cc]);
    }

#pragma unroll
    for (int rr = 0; rr < 4; rr++) {
        int row = rowBase + rg * 4 + rr;
        bool ok = row < NN;
        if (ok) {
            float4 hv = make_float4(acc[rr][0], acc[rr][1], acc[rr][2], acc[rr][3]);
            *reinterpret_cast<float4*>(&H[(size_t)row * 64 + cg * 4]) = hv;
        }
        float ps = 0.f, pd = 0.f;
#pragma unroll
        for (int cc = 0; cc < 4; cc++) {
            ps = fmaf(acc[rr][cc], aw_s[cc], ps);
            pd = fmaf(acc[rr][cc], aw_d[cc], pd);
        }
        if (LAYER == 1) {
            ps += __shfl_xor_sync(0xffffffffu, ps, 1);
            pd += __shfl_xor_sync(0xffffffffu, pd, 1);
            if (!(cg & 1) && ok) {
                g_as1[row * 8 + (cg >> 1)] = ps;
                g_ad1[row * 8 + (cg >> 1)] = pd;
            }
        } else {
            ps += __shfl_xor_sync(0xffffffffu, ps, 1);
            pd += __shfl_xor_sync(0xffffffffu, pd, 1);
            ps += __shfl_xor_sync(0xffffffffu, ps, 2);
            pd += __shfl_xor_sync(0xffffffffu, pd, 2);
            ps += __shfl_xor_sync(0xffffffffu, ps, 4);
            pd += __shfl_xor_sync(0xffffffffu, pd, 4);
            ps += __shfl_xor_sync(0xffffffffu, ps, 8);
            pd += __shfl_xor_sync(0xffffffffu, pd, 8);
            if (cg == 0 && ok) {
                g_as2[row] = ps;
                g_ad2[row] = pd;
            }
        }
    }
}

// ---------------- layer-1 aggregation: warp per dst, unroll 4 ----------------
__global__ __launch_bounds__(256) void agg1_kernel(const float* __restrict__ bias) {
    int warp = (blockIdx.x * blockDim.x + threadIdx.x) >> 5;
    int lane = threadIdx.x & 31;
    if (warp >= NN) return;
    int d = warp;
    int beg = g_off[d], end = g_off[d + 1];

    int laneH = lane & 7;  // safe index for all lanes; only lanes<8 values used
    float adh = g_ad1[d * 8 + laneH];
    int h0 = lane >> 3;
    int h1i = 4 + (lane >> 3);

    float num0 = 0.f, num1 = 0.f, den0 = 0.f, den1 = 0.f;
    float num0b = 0.f, num1b = 0.f, den0b = 0.f, den1b = 0.f;
    int i = beg;
    for (; i + 3 < end; i += 4) {
        int s0 = g_csr_src[i];
        int s1 = g_csr_src[i + 1];
        int s2 = g_csr_src[i + 2];
        int s3 = g_csr_src[i + 3];
        float a0 = g_as1[s0 * 8 + laneH];
        float a1 = g_as1[s1 * 8 + laneH];
        float a2 = g_as1[s2 * 8 + laneH];
        float a3 = g_as1[s3 * 8 + laneH];
        float v00 = g_h1[s0 * 64 + lane];
        float v01 = g_h1[s0 * 64 + 32 + lane];
        float v10 = g_h1[s1 * 64 + lane];
        float v11 = g_h1[s1 * 64 + 32 + lane];
        float v20 = g_h1[s2 * 64 + lane];
        float v21 = g_h1[s2 * 64 + 32 + lane];
        float v30 = g_h1[s3 * 64 + lane];
        float v31 = g_h1[s3 * 64 + 32 + lane];
        float x0 = __expf(lrelu(a0 + adh));
        float x1 = __expf(lrelu(a1 + adh));
        float x2 = __expf(lrelu(a2 + adh));
        float x3 = __expf(lrelu(a3 + adh));
        float e00 = __shfl_sync(0xffffffffu, x0, h0);
        float e01 = __shfl_sync(0xffffffffu, x0, h1i);
        float e10 = __shfl_sync(0xffffffffu, x1, h0);
        float e11 = __shfl_sync(0xffffffffu, x1, h1i);
        float e20 = __shfl_sync(0xffffffffu, x2, h0);
        float e21 = __shfl_sync(0xffffffffu, x2, h1i);
        float e30 = __shfl_sync(0xffffffffu, x3, h0);
        float e31 = __shfl_sync(0xffffffffu, x3, h1i);
        num0  = fmaf(e00, v00, num0);  den0  += e00;
        num1  = fmaf(e01, v01, num1);  den1  += e01;
        num0b = fmaf(e10, v10, num0b); den0b += e10;
        num1b = fmaf(e11, v11, num1b); den1b += e11;
        num0  = fmaf(e20, v20, num0);  den0  += e20;
        num1  = fmaf(e21, v21, num1);  den1  += e21;
        num0b = fmaf(e30, v30, num0b); den0b += e30;
        num1b = fmaf(e31, v31, num1b); den1b += e31;
    }
    for (; i < end; i++) {
        int s0 = g_csr_src[i];
        float a0 = g_as1[s0 * 8 + laneH];
        float v00 = g_h1[s0 * 64 + lane];
        float v01 = g_h1[s0 * 64 + 32 + lane];
        float x0 = __expf(lrelu(a0 + adh));
        float e00 = __shfl_sync(0xffffffffu, x0, h0);
        float e01 = __shfl_sync(0xffffffffu, x0, h1i);
        num0 = fmaf(e00, v00, num0); den0 += e00;
        num1 = fmaf(e01, v01, num1); den1 += e01;
    }
    num0 += num0b; den0 += den0b;
    num1 += num1b; den1 += den1b;
    float o0 = num0 / fmaxf(den0, 1e-16f) + bias[lane];
    float o1 = num1 / fmaxf(den1, 1e-16f) + bias[32 + lane];
    g_z1[d * 64 + lane]      = o0 > 0.f ? o0 : expm1f(o0);  // ELU
    g_z1[d * 64 + 32 + lane] = o1 > 0.f ? o1 : expm1f(o1);
}

// ---------------- layer-2 aggregation: warp per dst, unroll 4 ----------------
__global__ __launch_bounds__(256) void agg2_kernel(const float* __restrict__ bias) {
    int warp = (blockIdx.x * blockDim.x + threadIdx.x) >> 5;
    int lane = threadIdx.x & 31;
    if (warp >= NN) return;
    int d = warp;
    int beg = g_off[d], end = g_off[d + 1];

    float ad = g_ad2[d];
    float num0 = 0.f, num1 = 0.f, den = 0.f;
    float num0b = 0.f, num1b = 0.f, denb = 0.f;
    int i = beg;
    for (; i + 3 < end; i += 4) {
        int s0 = g_csr_src[i];
        int s1 = g_csr_src[i + 1];
        int s2 = g_csr_src[i + 2];
        int s3 = g_csr_src[i + 3];
        float a0 = g_as2[s0];
        float a1 = g_as2[s1];
        float a2 = g_as2[s2];
        float a3 = g_as2[s3];
        float v00 = g_h2[s0 * 64 + lane];
        float v01 = g_h2[s0 * 64 + 32 + lane];
        float v10 = g_h2[s1 * 64 + lane];
        float v11 = g_h2[s1 * 64 + 32 + lane];
        float v20 = g_h2[s2 * 64 + lane];
        float v21 = g_h2[s2 * 64 + 32 + lane];
        float v30 = g_h2[s3 * 64 + lane];
        float v31 = g_h2[s3 * 64 + 32 + lane];
        float e0 = __expf(lrelu(a0 + ad));
        float e1 = __expf(lrelu(a1 + ad));
        float e2 = __expf(lrelu(a2 + ad));
        float e3 = __expf(lrelu(a3 + ad));
        num0  = fmaf(e0, v00, num0);  num1  = fmaf(e0, v01, num1);  den  += e0;
        num0b = fmaf(e1, v10, num0b); num1b = fmaf(e1, v11, num1b); denb += e1;
        num0  = fmaf(e2, v20, num0);  num1  = fmaf(e2, v21, num1);  den  += e2;
        num0b = fmaf(e3, v30, num0b); num1b = fmaf(e3, v31, num1b); denb += e3;
    }
    for (; i < end; i++) {
        int s0 = g_csr_src[i];
        float e0 = __expf(lrelu(g_as2[s0] + ad));
        num0 = fmaf(e0, g_h2[s0 * 64 + lane], num0);
        num1 = fmaf(e0, g_h2[s0 * 64 + 32 + lane], num1);
        den += e0;
    }
    num0 += num0b; num1 += num1b; den += denb;
    float inv = 1.0f / fmaxf(den, 1e-16f);
    g_z2[d * 64 + lane]      = num0 * inv + bias[lane];
    g_z2[d * 64 + 32 + lane] = num1 * inv + bias[32 + lane];
}

// ---------------- link prediction logits -----------------------------------
__global__ __launch_bounds__(256) void logits_kernel(const int* __restrict__ pos,
                                                     const int* __restrict__ neg,
                                                     float* __restrict__ out) {
    int t = blockIdx.x * blockDim.x + threadIdx.x;
    if (t >= ETOT) return;
    int s, d;
    if (t < ETEST) { s = pos[t]; d = pos[ETEST + t]; }
    else           { s = neg[t - ETEST]; d = neg[ETEST + (t - ETEST)]; }
    const float4* a = reinterpret_cast<const float4*>(g_z2) + (size_t)s * 16;
    const float4* b = reinterpret_cast<const float4*>(g_z2) + (size_t)d * 16;
    float acc = 0.f;
#pragma unroll
    for (int i = 0; i < 16; i++) acc += dot4(a[i], b[i]);
    out[t] = acc;
}

// ---------------- launch ----------------------------------------------------
extern "C" void kernel_launch(void* const* d_in, const int* in_sizes, int n_in,
                              void* d_out, int out_size) {
    const float* x    = (const float*)d_in[0];
    const int*   ei   = (const int*)d_in[1];
    const int*   pos  = (const int*)d_in[2];
    const int*   neg  = (const int*)d_in[3];
    const float* W1   = (const float*)d_in[4];
    const float* as1  = (const float*)d_in[5];
    const float* ad1  = (const float*)d_in[6];
    const float* b1   = (const float*)d_in[7];
    const float* W2   = (const float*)d_in[8];
    const float* as2  = (const float*)d_in[9];
    const float* ad2  = (const float*)d_in[10];
    const float* b2   = (const float*)d_in[11];
    float* out = (float*)d_out;

    const int TB = 256;
    const int E4 = (E2 + 3) / 4;
    // CSR build
    zero_deg<<<(NN + TB - 1) / TB, TB>>>();
    count_deg<<<(E4 + TB - 1) / TB, TB>>>(ei);
    scan_kernel<<<1, 1024>>>();
    scatter_kernel<<<(E4 + TB - 1) / TB, TB>>>(ei);
    // layer 1 (GEMM + att fused)
    gemm_att<128, 1><<<(NN + 63) / 64, TB>>>(x, W1, as1, ad1);
    agg1_kernel<<<(NN * 32 + TB - 1) / TB, TB>>>(b1);
    // layer 2
    gemm_att<64, 2><<<(NN + 63) / 64, TB>>>(nullptr, W2, as2, ad2);
    agg2_kernel<<<(NN * 32 + TB - 1) / TB, TB>>>(b2);
    // logits
    logits_kernel<<<(ETOT + TB - 1) / TB, TB>>>(pos, neg, out);
}

// round 9
// speedup vs baseline: 1.3729x; 1.1851x over previous
#include <cuda_runtime.h>
#include <math.h>
#include <float.h>

#define NN 50000
#define EE 800000
#define E2 (EE + NN)      // edges + self loops = 850000
#define ETEST 100000
#define ETOT 200000

// ---------------- scratch (device globals) ----------------------------------
__device__ __align__(16) float g_h1[NN * 64];
__device__ __align__(16) float g_as1[NN * 8];
__device__ __align__(16) float g_ad1[NN * 8];
__device__ __align__(16) float g_z1[NN * 64];

__device__ __align__(16) float g_h2[NN * 64];
__device__ __align__(16) float g_as2[NN];
__device__ __align__(16) float g_ad2[NN];
__device__ __align__(16) float g_z2[NN * 64];

__device__ __align__(16) int g_deg[NN];
__device__ __align__(16) int g_off[NN + 1];
__device__ __align__(16) int g_epos[E2];
__device__ __align__(16) int g_csr_src[E2];

// ---------------- helpers --------------------------------------------------
__device__ __forceinline__ float lrelu(float x) { return x > 0.0f ? x : 0.2f * x; }

__device__ __forceinline__ float dot4(float4 a, float4 b) {
    return fmaf(a.x, b.x, fmaf(a.y, b.y, fmaf(a.z, b.z, a.w * b.w)));
}

// ---------------- CSR build -------------------------------------------------
__global__ void zero_deg() {
    int t = blockIdx.x * blockDim.x + threadIdx.x;
    if (t < NN) g_deg[t] = 0;
}

// count + record per-edge intra-bucket position (makes scatter atomic-free)
__global__ __launch_bounds__(256) void count_deg(const int* __restrict__ ei) {
    int e0 = (blockIdx.x * blockDim.x + threadIdx.x) * 4;
#pragma unroll
    for (int j = 0; j < 4; j++) {
        int e = e0 + j;
        if (e < E2) {
            int d = (e < EE) ? ei[EE + e] : (e - EE);
            g_epos[e] = atomicAdd(&g_deg[d], 1);
        }
    }
}

__global__ void scan_kernel() {
    __shared__ int ssum[1024];
    const int CH = (NN + 1023) / 1024;  // 49
    int t = threadIdx.x;
    int base = t * CH;
    int s = 0;
    for (int i = 0; i < CH; i++) {
        int idx = base + i;
        if (idx < NN) s += g_deg[idx];
    }
    ssum[t] = s;
    __syncthreads();
    for (int off = 1; off < 1024; off <<= 1) {
        int v = (t >= off) ? ssum[t - off] : 0;
        __syncthreads();
        ssum[t] += v;
        __syncthreads();
    }
    int run = (t == 0) ? 0 : ssum[t - 1];
    for (int i = 0; i < CH; i++) {
        int idx = base + i;
        if (idx < NN) {
            g_off[idx] = run;
            run += g_deg[idx];
        }
    }
    if (t == 1023) g_off[NN] = E2;
}

// atomic-free scatter: position = off[d] + epos[e]
__global__ __launch_bounds__(256) void scatter_kernel(const int* __restrict__ ei) {
    int e0 = (blockIdx.x * blockDim.x + threadIdx.x) * 4;
#pragma unroll
    for (int j = 0; j < 4; j++) {
        int e = e0 + j;
        if (e < E2) {
            int s, d;
            if (e < EE) { s = ei[e]; d = ei[EE + e]; }
            else        { s = e - EE; d = s; }
            g_csr_src[g_off[d] + g_epos[e]] = s;
        }
    }
}

// ---------------- fused GEMM + attention scores ------------------------------
// [NN,K] @ [K,64]; block tile 64 rows x 64 cols, 256 threads, thread tile 4x4.
template <int K, int LAYER>
__global__ __launch_bounds__(256) void gemm_att(
        const float* __restrict__ Xin, const float* __restrict__ W,
        const float* __restrict__ att_s, const float* __restrict__ att_d) {
    __shared__ float xs[64 * 64];
    __shared__ float ws[64 * 64];
    const float* X = (LAYER == 1) ? Xin : g_z1;
    float* H = (LAYER == 1) ? g_h1 : g_h2;

    int tid = threadIdx.x;
    int cg = tid & 15;        // col group (4 cols)
    int rg = tid >> 4;        // row group (4 rows)
    int rowBase = blockIdx.x * 64;

    float acc[4][4];
#pragma unroll
    for (int a = 0; a < 4; a++)
#pragma unroll
        for (int b = 0; b < 4; b++) acc[a][b] = 0.f;

    const float4* X4 = reinterpret_cast<const float4*>(X);
    const float4* W4 = reinterpret_cast<const float4*>(W);

    for (int kc = 0; kc < K; kc += 64) {
#pragma unroll
        for (int i = tid; i < 1024; i += 256) {
            int row = i >> 4, q = i & 15;
            float4 v = (rowBase + row < NN)
                ? X4[(size_t)(rowBase + row) * (K / 4) + (kc / 4) + q]
                : make_float4(0.f, 0.f, 0.f, 0.f);
            *reinterpret_cast<float4*>(&xs[row * 64 + q * 4]) = v;
        }
#pragma unroll
        for (int i = tid; i < 1024; i += 256) {
            *reinterpret_cast<float4*>(&ws[i * 4]) = W4[kc * 16 + i];
        }
        __syncthreads();

#pragma unroll 4
        for (int k = 0; k < 64; k++) {
            float4 wv = *reinterpret_cast<const float4*>(&ws[k * 64 + cg * 4]);
            float x0 = xs[(rg * 4 + 0) * 64 + k];
            float x1 = xs[(rg * 4 + 1) * 64 + k];
            float x2 = xs[(rg * 4 + 2) * 64 + k];
            float x3 = xs[(rg * 4 + 3) * 64 + k];
            acc[0][0] = fmaf(x0, wv.x, acc[0][0]); acc[0][1] = fmaf(x0, wv.y, acc[0][1]);
            acc[0][2] = fmaf(x0, wv.z, acc[0][2]); acc[0][3] = fmaf(x0, wv.w, acc[0][3]);
            acc[1][0] = fmaf(x1, wv.x, acc[1][0]); acc[1][1] = fmaf(x1, wv.y, acc[1][1]);
            acc[1][2] = fmaf(x1, wv.z, acc[1][2]); acc[1][3] = fmaf(x1, wv.w, acc[1][3]);
            acc[2][0] = fmaf(x2, wv.x, acc[2][0]); acc[2][1] = fmaf(x2, wv.y, acc[2][1]);
            acc[2][2] = fmaf(x2, wv.z, acc[2][2]); acc[2][3] = fmaf(x2, wv.w, acc[2][3]);
            acc[3][0] = fmaf(x3, wv.x, acc[3][0]); acc[3][1] = fmaf(x3, wv.y, acc[3][1]);
            acc[3][2] = fmaf(x3, wv.z, acc[3][2]); acc[3][3] = fmaf(x3, wv.w, acc[3][3]);
        }
        __syncthreads();
    }

    float aw_s[4], aw_d[4];
#pragma unroll
    for (int cc = 0; cc < 4; cc++) {
        aw_s[cc] = __ldg(&att_s[cg * 4 + cc]);
        aw_d[cc] = __ldg(&att_d[cg * 4 + cc]);
    }

#pragma unroll
    for (int rr = 0; rr < 4; rr++) {
        int row = rowBase + rg * 4 + rr;
        bool ok = row < NN;
        if (ok) {
            float4 hv = make_float4(acc[rr][0], acc[rr][1], acc[rr][2], acc[rr][3]);
            *reinterpret_cast<float4*>(&H[(size_t)row * 64 + cg * 4]) = hv;
        }
        float ps = 0.f, pd = 0.f;
#pragma unroll
        for (int cc = 0; cc < 4; cc++) {
            ps = fmaf(acc[rr][cc], aw_s[cc], ps);
            pd = fmaf(acc[rr][cc], aw_d[cc], pd);
        }
        if (LAYER == 1) {
            ps += __shfl_xor_sync(0xffffffffu, ps, 1);
            pd += __shfl_xor_sync(0xffffffffu, pd, 1);
            if (!(cg & 1) && ok) {
                g_as1[row * 8 + (cg >> 1)] = ps;
                g_ad1[row * 8 + (cg >> 1)] = pd;
            }
        } else {
            ps += __shfl_xor_sync(0xffffffffu, ps, 1);
            pd += __shfl_xor_sync(0xffffffffu, pd, 1);
            ps += __shfl_xor_sync(0xffffffffu, ps, 2);
            pd += __shfl_xor_sync(0xffffffffu, pd, 2);
            ps += __shfl_xor_sync(0xffffffffu, ps, 4);
            pd += __shfl_xor_sync(0xffffffffu, pd, 4);
            ps += __shfl_xor_sync(0xffffffffu, ps, 8);
            pd += __shfl_xor_sync(0xffffffffu, pd, 8);
            if (cg == 0 && ok) {
                g_as2[row] = ps;
                g_ad2[row] = pd;
            }
        }
    }
}

// ---------------- layer-1 aggregation: warp/dst, channel-pair layout ---------
// lane handles channels {2*lane, 2*lane+1}; both in head lane>>2 -> 1 shfl/edge.
__global__ __launch_bounds__(256) void agg1_kernel(const float* __restrict__ bias) {
    int warp = (blockIdx.x * blockDim.x + threadIdx.x) >> 5;
    int lane = threadIdx.x & 31;
    if (warp >= NN) return;
    int d = warp;
    int beg = g_off[d], end = g_off[d + 1];

    int laneH = lane & 7;          // score index this lane loads (valid all lanes)
    float adh = g_ad1[d * 8 + laneH];
    int hh = lane >> 2;            // head of channels 2*lane, 2*lane+1

    const float2* H2 = reinterpret_cast<const float2*>(g_h1);
    float2 numA = make_float2(0.f, 0.f), numB = make_float2(0.f, 0.f);
    float denA = 0.f, denB = 0.f;
    int i = beg;
    for (; i + 3 < end; i += 4) {
        int s0 = g_csr_src[i];
        int s1 = g_csr_src[i + 1];
        int s2 = g_csr_src[i + 2];
        int s3 = g_csr_src[i + 3];
        float a0 = g_as1[s0 * 8 + laneH];
        float a1 = g_as1[s1 * 8 + laneH];
        float a2 = g_as1[s2 * 8 + laneH];
        float a3 = g_as1[s3 * 8 + laneH];
        float2 v0 = H2[s0 * 32 + lane];
        float2 v1 = H2[s1 * 32 + lane];
        float2 v2 = H2[s2 * 32 + lane];
        float2 v3 = H2[s3 * 32 + lane];
        float x0 = __expf(lrelu(a0 + adh));
        float x1 = __expf(lrelu(a1 + adh));
        float x2 = __expf(lrelu(a2 + adh));
        float x3 = __expf(lrelu(a3 + adh));
        float e0 = __shfl_sync(0xffffffffu, x0, hh);
        float e1 = __shfl_sync(0xffffffffu, x1, hh);
        float e2 = __shfl_sync(0xffffffffu, x2, hh);
        float e3 = __shfl_sync(0xffffffffu, x3, hh);
        numA.x = fmaf(e0, v0.x, numA.x); numA.y = fmaf(e0, v0.y, numA.y); denA += e0;
        numB.x = fmaf(e1, v1.x, numB.x); numB.y = fmaf(e1, v1.y, numB.y); denB += e1;
        numA.x = fmaf(e2, v2.x, numA.x); numA.y = fmaf(e2, v2.y, numA.y); denA += e2;
        numB.x = fmaf(e3, v3.x, numB.x); numB.y = fmaf(e3, v3.y, numB.y); denB += e3;
    }
    for (; i < end; i++) {
        int s0 = g_csr_src[i];
        float a0 = g_as1[s0 * 8 + laneH];
        float2 v0 = H2[s0 * 32 + lane];
        float x0 = __expf(lrelu(a0 + adh));
        float e0 = __shfl_sync(0xffffffffu, x0, hh);
        numA.x = fmaf(e0, v0.x, numA.x); numA.y = fmaf(e0, v0.y, numA.y); denA += e0;
    }
    float den = denA + denB;
    float inv = 1.0f / fmaxf(den, 1e-16f);
    const float2* B2 = reinterpret_cast<const float2*>(bias);
    float2 bv = B2[lane];
    float o0 = (numA.x + numB.x) * inv + bv.x;
    float o1 = (numA.y + numB.y) * inv + bv.y;
    float2 ov;
    ov.x = o0 > 0.f ? o0 : expm1f(o0);   // ELU
    ov.y = o1 > 0.f ? o1 : expm1f(o1);
    reinterpret_cast<float2*>(g_z1)[d * 32 + lane] = ov;
}

// ---------------- layer-2 aggregation: warp/dst, channel-pair layout ---------
__global__ __launch_bounds__(256) void agg2_kernel(const float* __restrict__ bias) {
    int warp = (blockIdx.x * blockDim.x + threadIdx.x) >> 5;
    int lane = threadIdx.x & 31;
    if (warp >= NN) return;
    int d = warp;
    int beg = g_off[d], end = g_off[d + 1];

    float ad = g_ad2[d];
    const float2* H2 = reinterpret_cast<const float2*>(g_h2);
    float2 numA = make_float2(0.f, 0.f), numB = make_float2(0.f, 0.f);
    float denA = 0.f, denB = 0.f;
    int i = beg;
    for (; i + 3 < end; i += 4) {
        int s0 = g_csr_src[i];
        int s1 = g_csr_src[i + 1];
        int s2 = g_csr_src[i + 2];
        int s3 = g_csr_src[i + 3];
        float a0 = g_as2[s0];
        float a1 = g_as2[s1];
        float a2 = g_as2[s2];
        float a3 = g_as2[s3];
        float2 v0 = H2[s0 * 32 + lane];
        float2 v1 = H2[s1 * 32 + lane];
        float2 v2 = H2[s2 * 32 + lane];
        float2 v3 = H2[s3 * 32 + lane];
        float e0 = __expf(lrelu(a0 + ad));
        float e1 = __expf(lrelu(a1 + ad));
        float e2 = __expf(lrelu(a2 + ad));
        float e3 = __expf(lrelu(a3 + ad));
        numA.x = fmaf(e0, v0.x, numA.x); numA.y = fmaf(e0, v0.y, numA.y); denA += e0;
        numB.x = fmaf(e1, v1.x, numB.x); numB.y = fmaf(e1, v1.y, numB.y); denB += e1;
        numA.x = fmaf(e2, v2.x, numA.x); numA.y = fmaf(e2, v2.y, numA.y); denA += e2;
        numB.x = fmaf(e3, v3.x, numB.x); numB.y = fmaf(e3, v3.y, numB.y); denB += e3;
    }
    for (; i < end; i++) {
        int s0 = g_csr_src[i];
        float2 v0 = H2[s0 * 32 + lane];
        float e0 = __expf(lrelu(g_as2[s0] + ad));
        numA.x = fmaf(e0, v0.x, numA.x); numA.y = fmaf(e0, v0.y, numA.y); denA += e0;
    }
    float inv = 1.0f / fmaxf(denA + denB, 1e-16f);
    const float2* B2 = reinterpret_cast<const float2*>(bias);
    float2 bv = B2[lane];
    float2 ov;
    ov.x = (numA.x + numB.x) * inv + bv.x;
    ov.y = (numA.y + numB.y) * inv + bv.y;
    reinterpret_cast<float2*>(g_z2)[d * 32 + lane] = ov;
}

// ---------------- link prediction logits -----------------------------------
__global__ __launch_bounds__(256) void logits_kernel(const int* __restrict__ pos,
                                                     const int* __restrict__ neg,
                                                     float* __restrict__ out) {
    int t = blockIdx.x * blockDim.x + threadIdx.x;
    if (t >= ETOT) return;
    int s, d;
    if (t < ETEST) { s = pos[t]; d = pos[ETEST + t]; }
    else           { s = neg[t - ETEST]; d = neg[ETEST + (t - ETEST)]; }
    const float4* a = reinterpret_cast<const float4*>(g_z2) + (size_t)s * 16;
    const float4* b = reinterpret_cast<const float4*>(g_z2) + (size_t)d * 16;
    float acc = 0.f;
#pragma unroll
    for (int i = 0; i < 16; i++) acc += dot4(a[i], b[i]);
    out[t] = acc;
}

// ---------------- launch ----------------------------------------------------
extern "C" void kernel_launch(void* const* d_in, const int* in_sizes, int n_in,
                              void* d_out, int out_size) {
    const float* x    = (const float*)d_in[0];
    const int*   ei   = (const int*)d_in[1];
    const int*   pos  = (const int*)d_in[2];
    const int*   neg  = (const int*)d_in[3];
    const float* W1   = (const float*)d_in[4];
    const float* as1  = (const float*)d_in[5];
    const float* ad1  = (const float*)d_in[6];
    const float* b1   = (const float*)d_in[7];
    const float* W2   = (const float*)d_in[8];
    const float* as2  = (const float*)d_in[9];
    const float* ad2  = (const float*)d_in[10];
    const float* b2   = (const float*)d_in[11];
    float* out = (float*)d_out;

    const int TB = 256;
    const int E4 = (E2 + 3) / 4;
    // CSR build
    zero_deg<<<(NN + TB - 1) / TB, TB>>>();
    count_deg<<<(E4 + TB - 1) / TB, TB>>>(ei);
    scan_kernel<<<1, 1024>>>();
    scatter_kernel<<<(E4 + TB - 1) / TB, TB>>>(ei);
    // layer 1 (GEMM + att fused)
    gemm_att<128, 1><<<(NN + 63) / 64, TB>>>(x, W1, as1, ad1);
    agg1_kernel<<<(NN * 32 + TB - 1) / TB, TB>>>(b1);
    // layer 2
    gemm_att<64, 2><<<(NN + 63) / 64, TB>>>(nullptr, W2, as2, ad2);
    agg2_kernel<<<(NN * 32 + TB - 1) / TB, TB>>>(b2);
    // logits
    logits_kernel<<<(ETOT + TB - 1) / TB, TB>>>(pos, neg, out);
}

// round 10
// speedup vs baseline: 1.5338x; 1.1172x over previous
#include <cuda_runtime.h>
#include <math.h>
#include <float.h>

#define NN 50000
#define EE 800000
#define E2 (EE + NN)      // edges + self loops = 850000
#define ETEST 100000
#define ETOT 200000

// ---------------- scratch (device globals) ----------------------------------
__device__ __align__(16) float g_h1[NN * 64];
__device__ __align__(16) float g_as1[NN * 8];
__device__ __align__(16) float g_ad1[NN * 8];
__device__ __align__(16) float g_z1[NN * 64];

__device__ __align__(16) float g_h2[NN * 64];
__device__ __align__(16) float g_as2[NN];
__device__ __align__(16) float g_ad2[NN];
__device__ __align__(16) float g_z2[NN * 64];

__device__ __align__(16) int g_deg[NN];
__device__ __align__(16) int g_off[NN + 1];
__device__ __align__(16) int g_epos[E2];
__device__ __align__(16) int g_csr_src[E2];

// ---------------- helpers --------------------------------------------------
__device__ __forceinline__ float lrelu(float x) { return x > 0.0f ? x : 0.2f * x; }

__device__ __forceinline__ float dot4(float4 a, float4 b) {
    return fmaf(a.x, b.x, fmaf(a.y, b.y, fmaf(a.z, b.z, a.w * b.w)));
}

// ---------------- CSR build -------------------------------------------------
__global__ void zero_deg() {
    int t = blockIdx.x * blockDim.x + threadIdx.x;
    if (t < NN) g_deg[t] = 0;
}

// count + record per-edge intra-bucket position (makes scatter atomic-free)
__global__ __launch_bounds__(256) void count_deg(const int* __restrict__ ei) {
    int e0 = (blockIdx.x * blockDim.x + threadIdx.x) * 4;
#pragma unroll
    for (int j = 0; j < 4; j++) {
        int e = e0 + j;
        if (e < E2) {
            int d = (e < EE) ? ei[EE + e] : (e - EE);
            g_epos[e] = atomicAdd(&g_deg[d], 1);
        }
    }
}

// single-block scan with coalesced smem staging (dynamic smem = NN ints)
__global__ void scan_kernel() {
    extern __shared__ int sdeg[];           // NN ints (200 KB)
    __shared__ int ssum[1024];
    const int CH = (NN + 1023) / 1024;      // 49
    int t = threadIdx.x;
    // coalesced stage-in
    for (int i = t; i < NN; i += 1024) sdeg[i] = g_deg[i];
    __syncthreads();
    int base = t * CH;
    int s = 0;
    for (int i = 0; i < CH; i++) {
        int idx = base + i;
        if (idx < NN) s += sdeg[idx];       // stride 49 mod 32 banks: conflict-free
    }
    ssum[t] = s;
    __syncthreads();
    for (int off = 1; off < 1024; off <<= 1) {
        int v = (t >= off) ? ssum[t - off] : 0;
        __syncthreads();
        ssum[t] += v;
        __syncthreads();
    }
    int run = (t == 0) ? 0 : ssum[t - 1];
    for (int i = 0; i < CH; i++) {
        int idx = base + i;
        if (idx < NN) {
            g_off[idx] = run;
            run += sdeg[idx];
        }
    }
    if (t == 1023) g_off[NN] = E2;
}

// atomic-free scatter: position = off[d] + epos[e]
__global__ __launch_bounds__(256) void scatter_kernel(const int* __restrict__ ei) {
    int e0 = (blockIdx.x * blockDim.x + threadIdx.x) * 4;
#pragma unroll
    for (int j = 0; j < 4; j++) {
        int e = e0 + j;
        if (e < E2) {
            int s, d;
            if (e < EE) { s = ei[e]; d = ei[EE + e]; }
            else        { s = e - EE; d = s; }
            g_csr_src[g_off[d] + g_epos[e]] = s;
        }
    }
}

// ---------------- fused GEMM + attention scores ------------------------------
template <int K, int LAYER>
__global__ __launch_bounds__(256) void gemm_att(
        const float* __restrict__ Xin, const float* __restrict__ W,
        const float* __restrict__ att_s, const float* __restrict__ att_d) {
    __shared__ float xs[64 * 64];
    __shared__ float ws[64 * 64];
    const float* X = (LAYER == 1) ? Xin : g_z1;
    float* H = (LAYER == 1) ? g_h1 : g_h2;

    int tid = threadIdx.x;
    int cg = tid & 15;        // col group (4 cols)
    int rg = tid >> 4;        // row group (4 rows)
    int rowBase = blockIdx.x * 64;

    float acc[4][4];
#pragma unroll
    for (int a = 0; a < 4; a++)
#pragma unroll
        for (int b = 0; b < 4; b++) acc[a][b] = 0.f;

    const float4* X4 = reinterpret_cast<const float4*>(X);
    const float4* W4 = reinterpret_cast<const float4*>(W);

    for (int kc = 0; kc < K; kc += 64) {
#pragma unroll
        for (int i = tid; i < 1024; i += 256) {
            int row = i >> 4, q = i & 15;
            float4 v = (rowBase + row < NN)
                ? X4[(size_t)(rowBase + row) * (K / 4) + (kc / 4) + q]
                : make_float4(0.f, 0.f, 0.f, 0.f);
            *reinterpret_cast<float4*>(&xs[row * 64 + q * 4]) = v;
        }
#pragma unroll
        for (int i = tid; i < 1024; i += 256) {
            *reinterpret_cast<float4*>(&ws[i * 4]) = W4[kc * 16 + i];
        }
        __syncthreads();

#pragma unroll 4
        for (int k = 0; k < 64; k++) {
            float4 wv = *reinterpret_cast<const float4*>(&ws[k * 64 + cg * 4]);
            float x0 = xs[(rg * 4 + 0) * 64 + k];
            float x1 = xs[(rg * 4 + 1) * 64 + k];
            float x2 = xs[(rg * 4 + 2) * 64 + k];
            float x3 = xs[(rg * 4 + 3) * 64 + k];
            acc[0][0] = fmaf(x0, wv.x, acc[0][0]); acc[0][1] = fmaf(x0, wv.y, acc[0][1]);
            acc[0][2] = fmaf(x0, wv.z, acc[0][2]); acc[0][3] = fmaf(x0, wv.w, acc[0][3]);
            acc[1][0] = fmaf(x1, wv.x, acc[1][0]); acc[1][1] = fmaf(x1, wv.y, acc[1][1]);
            acc[1][2] = fmaf(x1, wv.z, acc[1][2]); acc[1][3] = fmaf(x1, wv.w, acc[1][3]);
            acc[2][0] = fmaf(x2, wv.x, acc[2][0]); acc[2][1] = fmaf(x2, wv.y, acc[2][1]);
            acc[2][2] = fmaf(x2, wv.z, acc[2][2]); acc[2][3] = fmaf(x2, wv.w, acc[2][3]);
            acc[3][0] = fmaf(x3, wv.x, acc[3][0]); acc[3][1] = fmaf(x3, wv.y, acc[3][1]);
            acc[3][2] = fmaf(x3, wv.z, acc[3][2]); acc[3][3] = fmaf(x3, wv.w, acc[3][3]);
        }
        __syncthreads();
    }

    float aw_s[4], aw_d[4];
#pragma unroll
    for (int cc = 0; cc < 4; cc++) {
        aw_s[cc] = __ldg(&att_s[cg * 4 + cc]);
        aw_d[cc] = __ldg(&att_d[cg * 4 + cc]);
    }

#pragma unroll
    for (int rr = 0; rr < 4; rr++) {
        int row = rowBase + rg * 4 + rr;
        bool ok = row < NN;
        if (ok) {
            float4 hv = make_float4(acc[rr][0], acc[rr][1], acc[rr][2], acc[rr][3]);
            *reinterpret_cast<float4*>(&H[(size_t)row * 64 + cg * 4]) = hv;
        }
        float ps = 0.f, pd = 0.f;
#pragma unroll
        for (int cc = 0; cc < 4; cc++) {
            ps = fmaf(acc[rr][cc], aw_s[cc], ps);
            pd = fmaf(acc[rr][cc], aw_d[cc], pd);
        }
        if (LAYER == 1) {
            ps += __shfl_xor_sync(0xffffffffu, ps, 1);
            pd += __shfl_xor_sync(0xffffffffu, pd, 1);
            if (!(cg & 1) && ok) {
                g_as1[row * 8 + (cg >> 1)] = ps;
                g_ad1[row * 8 + (cg >> 1)] = pd;
            }
        } else {
            ps += __shfl_xor_sync(0xffffffffu, ps, 1);
            pd += __shfl_xor_sync(0xffffffffu, pd, 1);
            ps += __shfl_xor_sync(0xffffffffu, ps, 2);
            pd += __shfl_xor_sync(0xffffffffu, pd, 2);
            ps += __shfl_xor_sync(0xffffffffu, ps, 4);
            pd += __shfl_xor_sync(0xffffffffu, pd, 4);
            ps += __shfl_xor_sync(0xffffffffu, ps, 8);
            pd += __shfl_xor_sync(0xffffffffu, pd, 8);
            if (cg == 0 && ok) {
                g_as2[row] = ps;
                g_ad2[row] = pd;
            }
        }
    }
}

// ---------------- layer-1 aggregation: warp/dst, float2 lanes, unroll 8 ------
__global__ __launch_bounds__(256) void agg1_kernel(const float* __restrict__ bias) {
    int warp = (blockIdx.x * blockDim.x + threadIdx.x) >> 5;
    int lane = threadIdx.x & 31;
    if (warp >= NN) return;
    int d = warp;
    int beg = g_off[d], end = g_off[d + 1];

    int laneH = lane & 7;
    float adh = g_ad1[d * 8 + laneH];
    int hh = lane >> 2;  // head of channels 2*lane, 2*lane+1

    const float2* H2 = reinterpret_cast<const float2*>(g_h1);
    float2 numA = make_float2(0.f, 0.f), numB = make_float2(0.f, 0.f);
    float denA = 0.f, denB = 0.f;
    int i = beg;
    for (; i + 7 < end; i += 8) {
        int sIdx[8];
#pragma unroll
        for (int j = 0; j < 8; j++) sIdx[j] = g_csr_src[i + j];
        float aV[8]; float2 vV[8];
#pragma unroll
        for (int j = 0; j < 8; j++) {
            aV[j] = g_as1[sIdx[j] * 8 + laneH];
            vV[j] = H2[sIdx[j] * 32 + lane];
        }
#pragma unroll
        for (int j = 0; j < 8; j++) aV[j] = __expf(lrelu(aV[j] + adh));
#pragma unroll
        for (int j = 0; j < 8; j++) {
            float e = __shfl_sync(0xffffffffu, aV[j], hh);
            if (j & 1) { numB.x = fmaf(e, vV[j].x, numB.x); numB.y = fmaf(e, vV[j].y, numB.y); denB += e; }
            else       { numA.x = fmaf(e, vV[j].x, numA.x); numA.y = fmaf(e, vV[j].y, numA.y); denA += e; }
        }
    }
    for (; i < end; i++) {
        int s0 = g_csr_src[i];
        float a0 = g_as1[s0 * 8 + laneH];
        float2 v0 = H2[s0 * 32 + lane];
        float x0 = __expf(lrelu(a0 + adh));
        float e0 = __shfl_sync(0xffffffffu, x0, hh);
        numA.x = fmaf(e0, v0.x, numA.x); numA.y = fmaf(e0, v0.y, numA.y); denA += e0;
    }
    float inv = 1.0f / fmaxf(denA + denB, 1e-16f);
    const float2* B2 = reinterpret_cast<const float2*>(bias);
    float2 bv = B2[lane];
    float o0 = (numA.x + numB.x) * inv + bv.x;
    float o1 = (numA.y + numB.y) * inv + bv.y;
    float2 ov;
    ov.x = o0 > 0.f ? o0 : expm1f(o0);   // ELU
    ov.y = o1 > 0.f ? o1 : expm1f(o1);
    reinterpret_cast<float2*>(g_z1)[d * 32 + lane] = ov;
}

// ---------------- layer-2 aggregation: warp/dst, float2 lanes, unroll 8 ------
__global__ __launch_bounds__(256) void agg2_kernel(const float* __restrict__ bias) {
    int warp = (blockIdx.x * blockDim.x + threadIdx.x) >> 5;
    int lane = threadIdx.x & 31;
    if (warp >= NN) return;
    int d = warp;
    int beg = g_off[d], end = g_off[d + 1];

    float ad = g_ad2[d];
    const float2* H2 = reinterpret_cast<const float2*>(g_h2);
    float2 numA = make_float2(0.f, 0.f), numB = make_float2(0.f, 0.f);
    float denA = 0.f, denB = 0.f;
    int i = beg;
    for (; i + 7 < end; i += 8) {
        int sIdx[8];
#pragma unroll
        for (int j = 0; j < 8; j++) sIdx[j] = g_csr_src[i + j];
        float aV[8]; float2 vV[8];
#pragma unroll
        for (int j = 0; j < 8; j++) {
            aV[j] = g_as2[sIdx[j]];
            vV[j] = H2[sIdx[j] * 32 + lane];
        }
#pragma unroll
        for (int j = 0; j < 8; j++) {
            float e = __expf(lrelu(aV[j] + ad));
            if (j & 1) { numB.x = fmaf(e, vV[j].x, numB.x); numB.y = fmaf(e, vV[j].y, numB.y); denB += e; }
            else       { numA.x = fmaf(e, vV[j].x, numA.x); numA.y = fmaf(e, vV[j].y, numA.y); denA += e; }
        }
    }
    for (; i < end; i++) {
        int s0 = g_csr_src[i];
        float2 v0 = H2[s0 * 32 + lane];
        float e0 = __expf(lrelu(g_as2[s0] + ad));
        numA.x = fmaf(e0, v0.x, numA.x); numA.y = fmaf(e0, v0.y, numA.y); denA += e0;
    }
    float inv = 1.0f / fmaxf(denA + denB, 1e-16f);
    const float2* B2 = reinterpret_cast<const float2*>(bias);
    float2 bv = B2[lane];
    float2 ov;
    ov.x = (numA.x + numB.x) * inv + bv.x;
    ov.y = (numA.y + numB.y) * inv + bv.y;
    reinterpret_cast<float2*>(g_z2)[d * 32 + lane] = ov;
}

// ---------------- link prediction logits: 16 threads per edge ----------------
__global__ __launch_bounds__(256) void logits_kernel(const int* __restrict__ pos,
                                                     const int* __restrict__ neg,
                                                     float* __restrict__ out) {
    int t = blockIdx.x * blockDim.x + threadIdx.x;
    int edge = t >> 4, sub = t & 15;
    if (edge >= ETOT) return;
    int s, d;
    if (edge < ETEST) { s = pos[edge]; d = pos[ETEST + edge]; }
    else              { s = neg[edge - ETEST]; d = neg[ETEST + (edge - ETEST)]; }
    const float4* Z4 = reinterpret_cast<const float4*>(g_z2);
    float4 a = Z4[(size_t)s * 16 + sub];
    float4 b = Z4[(size_t)d * 16 + sub];
    float p = dot4(a, b);
    p += __shfl_xor_sync(0xffffffffu, p, 1);
    p += __shfl_xor_sync(0xffffffffu, p, 2);
    p += __shfl_xor_sync(0xffffffffu, p, 4);
    p += __shfl_xor_sync(0xffffffffu, p, 8);
    if (sub == 0) out[edge] = p;
}

// ---------------- launch ----------------------------------------------------
extern "C" void kernel_launch(void* const* d_in, const int* in_sizes, int n_in,
                              void* d_out, int out_size) {
    const float* x    = (const float*)d_in[0];
    const int*   ei   = (const int*)d_in[1];
    const int*   pos  = (const int*)d_in[2];
    const int*   neg  = (const int*)d_in[3];
    const float* W1   = (const float*)d_in[4];
    const float* as1  = (const float*)d_in[5];
    const float* ad1  = (const float*)d_in[6];
    const float* b1   = (const float*)d_in[7];
    const float* W2   = (const float*)d_in[8];
    const float* as2  = (const float*)d_in[9];
    const float* ad2  = (const float*)d_in[10];
    const float* b2   = (const float*)d_in[11];
    float* out = (float*)d_out;

    const int TB = 256;
    const int E4 = (E2 + 3) / 4;
    const int SCAN_SMEM = NN * (int)sizeof(int);   // 200 KB dynamic smem
    cudaFuncSetAttribute(scan_kernel, cudaFuncAttributeMaxDynamicSharedMemorySize,
                         SCAN_SMEM);

    // CSR build
    zero_deg<<<(NN + TB - 1) / TB, TB>>>();
    count_deg<<<(E4 + TB - 1) / TB, TB>>>(ei);
    scan_kernel<<<1, 1024, SCAN_SMEM>>>();
    scatter_kernel<<<(E4 + TB - 1) / TB, TB>>>(ei);
    // layer 1 (GEMM + att fused)
    gemm_att<128, 1><<<(NN + 63) / 64, TB>>>(x, W1, as1, ad1);
    agg1_kernel<<<(NN * 32 + TB - 1) / TB, TB>>>(b1);
    // layer 2
    gemm_att<64, 2><<<(NN + 63) / 64, TB>>>(nullptr, W2, as2, ad2);
    agg2_kernel<<<(NN * 32 + TB - 1) / TB, TB>>>(b2);
    // logits (16 threads per test edge)
    logits_kernel<<<(ETOT * 16 + TB - 1) / TB, TB>>>(pos, neg, out);
}